// round 2
// baseline (speedup 1.0000x reference)
#include <cuda_runtime.h>
#include <float.h>
#include <math.h>

#define BATCH 4
#define NPTS  2048
#define KNN   80
#define FEAT  256
#define MLPO  1024
#define EPSV  1e-5f

// ---------------- scratch (static device globals; no allocation) ----------------
__device__ float g_xt[BATCH*NPTS*3];
__device__ float g_key[(size_t)BATCH*NPTS*NPTS];      // 64 MB gram/key scratch
__device__ int   g_idx[BATCH*NPTS*KNN];
__device__ float g_sq[BATCH*NPTS];
__device__ float g_y[BATCH*NPTS*128];
__device__ float g_c[BATCH*NPTS*128];
__device__ float g_hmax[BATCH*NPTS*128];
__device__ float g_hmin[BATCH*NPTS*128];
__device__ float g_pst[BATCH*NPTS*4*2];               // per-(point,group) partial sums
__device__ float g_ss[BATCH*MLPO*2];                  // per-(b,channel) scale/shift
__device__ float g_feats[BATCH*NPTS*FEAT];
__device__ float g_h[(size_t)BATCH*NPTS*MLPO];        // 32 MB MLP activations
__device__ float g_mmax[BATCH*8*MLPO];
__device__ float g_mmin[BATCH*8*MLPO];
__device__ float g_gp[BATCH*8*8*2];

// ---------------- helpers ----------------
__device__ __forceinline__ unsigned f2u(float f) {
    unsigned u = __float_as_uint(f);
    return (u & 0x80000000u) ? ~u : (u | 0x80000000u);
}

// ---------------- transpose x [B,3,N] -> xt [B,N,3] ----------------
__global__ void k_transpose(const float* __restrict__ x) {
    int i = blockIdx.x * 256 + threadIdx.x;           // over B*3*N
    if (i < BATCH*3*NPTS) {
        int b = i / (3*NPTS);
        int r = i % (3*NPTS);
        int c = r / NPTS, n = r % NPTS;
        g_xt[(b*NPTS + n)*3 + c] = x[i];
    }
}

// ---------------- squared norms of feature rows ----------------
__global__ void k_sq(int foff) {
    int p = blockIdx.x * 8 + (threadIdx.x >> 5);
    int lane = threadIdx.x & 31;
    if (p < BATCH*NPTS) {
        const float* r = &g_feats[(size_t)p*FEAT + foff];
        float v = r[lane], w = r[lane + 32];
        float s = v*v + w*w;
        #pragma unroll
        for (int o = 16; o; o >>= 1) s += __shfl_xor_sync(~0u, s, o);
        if (lane == 0) g_sq[p] = s;
    }
}

// ---------------- top-80 radix select (block of 256 threads; 2048 keys in smem) ----
// Deterministic: smem int atomics for histograms (counts only), parallel scans,
// output emitted in ascending-index order (matches jax.lax.top_k tie-break set).
__device__ void topk80(unsigned* sk, int b, int n) {
    __shared__ int hist[256];
    __shared__ int sgm[256], sem[256];
    __shared__ int sbroad[2];
    int tid = threadIdx.x;

    unsigned prefix = 0, maskacc = 0;
    int kneed = KNN;
    #pragma unroll
    for (int shift = 24; shift >= 0; shift -= 8) {
        hist[tid] = 0;
        __syncthreads();
        #pragma unroll
        for (int e = 0; e < 8; e++) {
            unsigned u = sk[tid*8 + e];
            if ((u & maskacc) == prefix) atomicAdd(&hist[(u >> shift) & 255], 1);
        }
        __syncthreads();
        // suffix-inclusive scan of hist (count of bytes >= tid)
        int h = hist[tid];
        sgm[tid] = h;
        __syncthreads();
        #pragma unroll
        for (int off = 1; off < 256; off <<= 1) {
            int a = (tid + off < 256) ? sgm[tid + off] : 0;
            __syncthreads();
            sgm[tid] += a;
            __syncthreads();
        }
        int incl = sgm[tid];          // sum over bytes >= tid
        int excl = incl - h;          // sum over bytes >  tid
        if (excl < kneed && kneed <= incl) {
            sbroad[0] = tid;          // selected byte
            sbroad[1] = kneed - excl; // remaining inside this byte
        }
        __syncthreads();
        prefix |= ((unsigned)sbroad[0]) << shift;
        maskacc |= (0xFFu << shift);
        kneed = sbroad[1];
        __syncthreads();
    }
    unsigned T = prefix;              // exact 80th-largest key
    // count per-thread
    int cg = 0, ce = 0;
    #pragma unroll
    for (int e = 0; e < 8; e++) {
        unsigned u = sk[tid*8 + e];
        cg += (u > T);
        ce += (u == T);
    }
    sgm[tid] = cg; sem[tid] = ce;
    __syncthreads();
    #pragma unroll
    for (int off = 1; off < 256; off <<= 1) {
        int a  = (tid >= off) ? sgm[tid - off] : 0;
        int b2 = (tid >= off) ? sem[tid - off] : 0;
        __syncthreads();
        sgm[tid] += a; sem[tid] += b2;
        __syncthreads();
    }
    int offG = sgm[tid] - cg;
    int offE = sem[tid] - ce;
    int totG = sgm[255];              // == 80 - kneed
    int* out = &g_idx[(b*NPTS + n)*KNN];
    #pragma unroll
    for (int e = 0; e < 8; e++) {
        int i = tid*8 + e;
        unsigned u = sk[i];
        if (u > T) {
            out[offG++] = i;
        } else if (u == T) {
            if (offE < kneed) out[totG + offE] = i;
            offE++;
        }
    }
}

// ---------------- kNN for layer 1 (C=3, fused distance) ----------------
__global__ void k_knn_small() {
    __shared__ float sx[NPTS], sy[NPTS], sz[NPTS];
    __shared__ unsigned sk[NPTS];
    int blk = blockIdx.x;
    int b = blk >> 11, n = blk & 2047;
    int tid = threadIdx.x;
    for (int i = tid; i < NPTS; i += 256) {
        const float* p = &g_xt[(b*NPTS + i)*3];
        sx[i] = p[0]; sy[i] = p[1]; sz[i] = p[2];
    }
    __syncthreads();
    float cx = sx[n], cy = sy[n], cz = sz[n];
    for (int i = tid; i < NPTS; i += 256) {
        float X = sx[i], Y = sy[i], Z = sz[i];
        // neg_dist + const(sq[n]) : same ranking
        float key = 2.f*(cx*X + cy*Y + cz*Z) - (X*X + Y*Y + Z*Z);
        sk[i] = f2u(key);
    }
    __syncthreads();
    topk80(sk, b, n);
}

// ---------------- key GEMM: key[b,n,m] = 2*<f_n,f_m> - sq[m]  (K=64) ----------------
__global__ void k_key_gemm(int foff) {
    __shared__ float As[8][128], Bs[8][128];
    int b = blockIdx.z;
    int row0 = blockIdx.y * 128, col0 = blockIdx.x * 128;
    int tid = threadIdx.x;
    int tx = tid & 15, ty = tid >> 4;
    const float* Ab = &g_feats[((size_t)(b*NPTS + row0))*FEAT + foff];
    const float* Bb = &g_feats[((size_t)(b*NPTS + col0))*FEAT + foff];
    int lr = tid >> 1, lc = (tid & 1) * 4;
    float acc[8][8] = {};
    for (int k0 = 0; k0 < 64; k0 += 8) {
        float4 av = *(const float4*)(Ab + (size_t)lr*FEAT + k0 + lc);
        float4 bv = *(const float4*)(Bb + (size_t)lr*FEAT + k0 + lc);
        As[lc+0][lr] = av.x; As[lc+1][lr] = av.y; As[lc+2][lr] = av.z; As[lc+3][lr] = av.w;
        Bs[lc+0][lr] = bv.x; Bs[lc+1][lr] = bv.y; Bs[lc+2][lr] = bv.z; Bs[lc+3][lr] = bv.w;
        __syncthreads();
        #pragma unroll
        for (int k = 0; k < 8; k++) {
            float a[8], bb[8];
            #pragma unroll
            for (int i = 0; i < 8; i++) a[i] = As[k][ty*8 + i];
            #pragma unroll
            for (int j = 0; j < 8; j++) bb[j] = Bs[k][tx*8 + j];
            #pragma unroll
            for (int i = 0; i < 8; i++)
                #pragma unroll
                for (int j = 0; j < 8; j++)
                    acc[i][j] += a[i] * bb[j];
        }
        __syncthreads();
    }
    #pragma unroll
    for (int i = 0; i < 8; i++) {
        int r = row0 + ty*8 + i;
        #pragma unroll
        for (int j = 0; j < 8; j++) {
            int c = col0 + tx*8 + j;
            g_key[((size_t)(b*NPTS + r))*NPTS + c] = 2.f*acc[i][j] - g_sq[b*NPTS + c];
        }
    }
}

// ---------------- kNN from precomputed key rows ----------------
__global__ void k_knn_row() {
    __shared__ unsigned sk[NPTS];
    int blk = blockIdx.x;
    int b = blk >> 11, n = blk & 2047;
    int tid = threadIdx.x;
    const float* row = &g_key[((size_t)(b*NPTS + n))*NPTS];
    for (int i = tid; i < NPTS; i += 256) sk[i] = f2u(row[i]);
    __syncthreads();
    topk80(sk, b, n);
}

// ---------------- prep: y = f@Wl^T, c = f@(Wr-Wl)^T  (W is [O,2C]) ----------------
__global__ void k_prep(int use_xt, int foff, int Cin, int O, const float* __restrict__ W) {
    __shared__ float sf[16*64];
    int p0 = blockIdx.x * 16;
    int tid = threadIdx.x;
    for (int i = tid; i < 16*Cin; i += blockDim.x) {
        int rr = i / Cin, cc = i % Cin;
        int p = p0 + rr;
        sf[rr*Cin + cc] = use_xt ? g_xt[p*3 + cc]
                                 : g_feats[(size_t)p*FEAT + foff + cc];
    }
    __syncthreads();
    const float* Wr = &W[tid * 2 * Cin];
    for (int r = 0; r < 16; r++) {
        const float* fr = &sf[r*Cin];
        float y = 0.f, cc2 = 0.f;
        #pragma unroll 4
        for (int c = 0; c < Cin; c++) {
            float fv = fr[c];
            float wl = Wr[c], wrr = Wr[Cin + c];
            y   += fv * wl;
            cc2 += fv * (wrr - wl);
        }
        g_y[(size_t)(p0 + r)*O + tid] = y;
        g_c[(size_t)(p0 + r)*O + tid] = cc2;
    }
}

// ---------------- edge pass: per (b,n,o) max/min over k + per-group partial stats --
__global__ void k_edge(int O) {
    __shared__ int sidx[KNN];
    int p = blockIdx.x;                     // b*N + n
    int tid = threadIdx.x;
    for (int i = tid; i < KNN; i += blockDim.x)       // FIX: strided (blockDim may be < KNN)
        sidx[i] = g_idx[p*KNN + i];
    __syncthreads();
    int b = p >> 11;
    const float* ybase = &g_y[((size_t)b*NPTS)*O];
    float c = g_c[(size_t)p*O + tid];
    float mx = -FLT_MAX, mn = FLT_MAX, s = 0.f, ss = 0.f;
    #pragma unroll 4
    for (int k = 0; k < KNN; k++) {
        int j = sidx[k];
        float v = ybase[(size_t)j*O + tid] + c;
        mx = fmaxf(mx, v);
        mn = fminf(mn, v);
        s += v;
        ss += v*v;
    }
    #pragma unroll
    for (int o = 16; o; o >>= 1) {
        s  += __shfl_xor_sync(~0u, s,  o);
        ss += __shfl_xor_sync(~0u, ss, o);
    }
    int lane = tid & 31, w = tid >> 5;      // group == warp (group width = 32 always)
    int G = O >> 5;
    if (lane == 0) {
        g_pst[((size_t)p*G + w)*2 + 0] = s;
        g_pst[((size_t)p*G + w)*2 + 1] = ss;
    }
    g_hmax[(size_t)p*O + tid] = mx;
    g_hmin[(size_t)p*O + tid] = mn;
}

// ---------------- GN stats reduce (deterministic tree) -> per-channel scale/shift --
__global__ void k_gnstats(int G, int O, const float* __restrict__ gamma,
                          const float* __restrict__ beta) {
    int b = blockIdx.x / G, g = blockIdx.x % G;
    int tid = threadIdx.x;
    float s = 0.f, ss = 0.f;
    for (int n = tid; n < NPTS; n += 256) {
        size_t base = (((size_t)(b*NPTS + n))*G + g)*2;
        s += g_pst[base]; ss += g_pst[base + 1];
    }
    __shared__ float rs[256], rss[256];
    rs[tid] = s; rss[tid] = ss;
    __syncthreads();
    for (int off = 128; off; off >>= 1) {
        if (tid < off) { rs[tid] += rs[tid+off]; rss[tid] += rss[tid+off]; }
        __syncthreads();
    }
    float invc = 1.f / ((float)NPTS * (float)KNN * 32.f);
    float mean = rs[0] * invc;
    float var  = rss[0] * invc - mean*mean;
    float r = rsqrtf(var + EPSV);
    if (tid < 32) {
        int o = g*32 + tid;
        float sg = gamma[o] * r;
        float tt = beta[o] - sg * mean;
        g_ss[(b*O + o)*2 + 0] = sg;
        g_ss[(b*O + o)*2 + 1] = tt;
    }
}

// ---------------- finalize: feats[...,off+o] = lrelu(s*h* + t) ----------------
__global__ void k_edge_final(int O, int off) {
    int i = blockIdx.x*256 + threadIdx.x;   // over B*N*O
    if (i < BATCH*NPTS*O) {
        int p = i / O, o = i % O;
        int b = p >> 11;
        float sg = g_ss[(b*O + o)*2], tt = g_ss[(b*O + o)*2 + 1];
        float h = (sg >= 0.f) ? g_hmax[i] : g_hmin[i];
        float v = sg*h + tt;
        v = (v > 0.f) ? v : 0.2f*v;
        g_feats[(size_t)p*FEAT + off + o] = v;
    }
}

// ---------------- MLP GEMM: h = feats @ Wm^T + bm  (8192x1024x256) ----------------
__global__ void k_mlp_gemm(const float* __restrict__ Wm, const float* __restrict__ bm) {
    __shared__ float As[8][128], Bs[8][128];
    int row0 = blockIdx.y * 128;            // over B*N = 8192
    int col0 = blockIdx.x * 128;            // over 1024
    int tid = threadIdx.x;
    int tx = tid & 15, ty = tid >> 4;
    int lr = tid >> 1, lc = (tid & 1) * 4;
    const float* Ab = &g_feats[(size_t)row0 * FEAT];
    const float* Bb = &Wm[(size_t)col0 * FEAT];
    float acc[8][8] = {};
    for (int k0 = 0; k0 < FEAT; k0 += 8) {
        float4 av = *(const float4*)(Ab + (size_t)lr*FEAT + k0 + lc);
        float4 bv = *(const float4*)(Bb + (size_t)lr*FEAT + k0 + lc);
        As[lc+0][lr] = av.x; As[lc+1][lr] = av.y; As[lc+2][lr] = av.z; As[lc+3][lr] = av.w;
        Bs[lc+0][lr] = bv.x; Bs[lc+1][lr] = bv.y; Bs[lc+2][lr] = bv.z; Bs[lc+3][lr] = bv.w;
        __syncthreads();
        #pragma unroll
        for (int k = 0; k < 8; k++) {
            float a[8], bb[8];
            #pragma unroll
            for (int i = 0; i < 8; i++) a[i] = As[k][ty*8 + i];
            #pragma unroll
            for (int j = 0; j < 8; j++) bb[j] = Bs[k][tx*8 + j];
            #pragma unroll
            for (int i = 0; i < 8; i++)
                #pragma unroll
                for (int j = 0; j < 8; j++)
                    acc[i][j] += a[i] * bb[j];
        }
        __syncthreads();
    }
    #pragma unroll
    for (int i = 0; i < 8; i++) {
        int r = row0 + ty*8 + i;
        #pragma unroll
        for (int j = 0; j < 8; j++) {
            int c = col0 + tx*8 + j;
            g_h[(size_t)r*MLPO + c] = acc[i][j] + bm[c];
        }
    }
}

// ---------------- MLP head partials: per (b,group,seg) stats and per-o max/min ----
__global__ void k_mlp_part() {
    int b = blockIdx.z, g = blockIdx.y, seg = blockIdx.x;
    int t = threadIdx.x;                    // 128 = channels in group
    float mx = -FLT_MAX, mn = FLT_MAX, s = 0.f, ss = 0.f;
    int o = g*128 + t;
    for (int n = seg*256; n < seg*256 + 256; n++) {
        float v = g_h[((size_t)(b*NPTS + n))*MLPO + o];
        mx = fmaxf(mx, v); mn = fminf(mn, v);
        s += v; ss += v*v;
    }
    g_mmax[(b*8 + seg)*MLPO + o] = mx;
    g_mmin[(b*8 + seg)*MLPO + o] = mn;
    __shared__ float rs[128], rss[128];
    rs[t] = s; rss[t] = ss;
    __syncthreads();
    for (int off = 64; off; off >>= 1) {
        if (t < off) { rs[t] += rs[t+off]; rss[t] += rss[t+off]; }
        __syncthreads();
    }
    if (t == 0) {
        g_gp[((b*8 + g)*8 + seg)*2 + 0] = rs[0];
        g_gp[((b*8 + g)*8 + seg)*2 + 1] = rss[0];
    }
}

__global__ void k_mlp_final(const float* __restrict__ gm, const float* __restrict__ bg,
                            float* __restrict__ out4) {
    int b = blockIdx.x >> 3, g = blockIdx.x & 7;
    int t = threadIdx.x;
    int o = g*128 + t;
    float S = 0.f, SS = 0.f;
    #pragma unroll
    for (int seg = 0; seg < 8; seg++) {
        S  += g_gp[((b*8 + g)*8 + seg)*2 + 0];
        SS += g_gp[((b*8 + g)*8 + seg)*2 + 1];
    }
    float mx = -FLT_MAX, mn = FLT_MAX;
    #pragma unroll
    for (int seg = 0; seg < 8; seg++) {
        mx = fmaxf(mx, g_mmax[(b*8 + seg)*MLPO + o]);
        mn = fminf(mn, g_mmin[(b*8 + seg)*MLPO + o]);
    }
    float invc = 1.f / ((float)NPTS * 128.f);
    float mean = S * invc;
    float var  = SS * invc - mean*mean;
    float r = rsqrtf(var + EPSV);
    float sg = gm[o] * r;
    float tt = bg[o] - sg * mean;
    float h = (sg >= 0.f) ? mx : mn;
    float v = sg*h + tt;
    out4[b*MLPO + o] = fmaxf(v, 0.f);
}

// ---------------- feats transpose -> x_features [B,256,N] ----------------
__global__ void k_featsT(float* __restrict__ outf) {
    __shared__ float tile[32][33];
    int c0 = blockIdx.x * 32, n0 = blockIdx.y * 32, b = blockIdx.z;
    for (int i = threadIdx.y; i < 32; i += 8)
        tile[i][threadIdx.x] = g_feats[((size_t)(b*NPTS + n0 + i))*FEAT + c0 + threadIdx.x];
    __syncthreads();
    for (int i = threadIdx.y; i < 32; i += 8)
        outf[((size_t)b*FEAT + c0 + i)*NPTS + n0 + threadIdx.x] = tile[threadIdx.x][i];
}

// ---------------- launch ----------------
extern "C" void kernel_launch(void* const* d_in, const int* in_sizes, int n_in,
                              void* d_out, int out_size) {
    const float* x  = (const float*)d_in[0];
    const float* W1 = (const float*)d_in[1];
    const float* g1 = (const float*)d_in[2];
    const float* b1 = (const float*)d_in[3];
    const float* W2 = (const float*)d_in[4];
    const float* g2 = (const float*)d_in[5];
    const float* b2 = (const float*)d_in[6];
    const float* W3 = (const float*)d_in[7];
    const float* g3 = (const float*)d_in[8];
    const float* b3 = (const float*)d_in[9];
    const float* Wm = (const float*)d_in[10];
    const float* bm = (const float*)d_in[11];
    const float* gm = (const float*)d_in[12];
    const float* bg = (const float*)d_in[13];
    float* out = (float*)d_out;

    k_transpose<<<96, 256>>>(x);

    // Layer 1: C=3 -> O=64, G=2
    k_knn_small<<<BATCH*NPTS, 256>>>();
    k_prep<<<BATCH*NPTS/16, 64>>>(1, 0, 3, 64, W1);
    k_edge<<<BATCH*NPTS, 64>>>(64);
    k_gnstats<<<BATCH*2, 256>>>(2, 64, g1, b1);
    k_edge_final<<<BATCH*NPTS*64/256, 256>>>(64, 0);

    // Layer 2: C=64 (x1) -> O=64, G=2
    k_sq<<<BATCH*NPTS/8, 256>>>(0);
    k_key_gemm<<<dim3(16,16,BATCH), 256>>>(0);
    k_knn_row<<<BATCH*NPTS, 256>>>();
    k_prep<<<BATCH*NPTS/16, 64>>>(0, 0, 64, 64, W2);
    k_edge<<<BATCH*NPTS, 64>>>(64);
    k_gnstats<<<BATCH*2, 256>>>(2, 64, g2, b2);
    k_edge_final<<<BATCH*NPTS*64/256, 256>>>(64, 64);

    // Layer 3: C=64 (x2) -> O=128, G=4
    k_sq<<<BATCH*NPTS/8, 256>>>(64);
    k_key_gemm<<<dim3(16,16,BATCH), 256>>>(64);
    k_knn_row<<<BATCH*NPTS, 256>>>();
    k_prep<<<BATCH*NPTS/16, 128>>>(0, 64, 64, 128, W3);
    k_edge<<<BATCH*NPTS, 128>>>(128);
    k_gnstats<<<BATCH*4, 256>>>(4, 128, g3, b3);
    k_edge_final<<<BATCH*NPTS*128/256, 256>>>(128, 128);

    // MLP head
    k_mlp_gemm<<<dim3(MLPO/128, BATCH*NPTS/128), 256>>>(Wm, bm);
    k_mlp_part<<<dim3(8, 8, BATCH), 128>>>();
    k_mlp_final<<<BATCH*8, 128>>>(gm, bg, out);

    // x_features output
    k_featsT<<<dim3(FEAT/32, NPTS/32, BATCH), dim3(32, 8)>>>(out + BATCH*MLPO);
}

// round 4
// speedup vs baseline: 1.1399x; 1.1399x over previous
#include <cuda_runtime.h>
#include <float.h>
#include <math.h>

#define BATCH 4
#define NPTS  2048
#define KNN   80
#define FEAT  256
#define MLPO  1024
#define EPSV  1e-5f
#define WPB   4          // warps (points) per knn block

// ---------------- scratch (static device globals; no allocation) ----------------
__device__ float g_xt[BATCH*NPTS*3];
__device__ float g_key[(size_t)BATCH*NPTS*NPTS];      // 64 MB gram/key scratch
__device__ int   g_idx[BATCH*NPTS*KNN];
__device__ float g_sq[BATCH*NPTS];
__device__ float g_y[BATCH*NPTS*128];
__device__ float g_c[BATCH*NPTS*128];
__device__ float g_hmax[BATCH*NPTS*128];
__device__ float g_hmin[BATCH*NPTS*128];
__device__ float g_pst[BATCH*NPTS*4*2];               // per-(point,group) partial sums
__device__ float g_ss[BATCH*MLPO*2];                  // per-(b,channel) scale/shift
__device__ float g_feats[BATCH*NPTS*FEAT];
__device__ float g_h[(size_t)BATCH*NPTS*MLPO];        // 32 MB MLP activations
__device__ float g_mmax[BATCH*8*MLPO];
__device__ float g_mmin[BATCH*8*MLPO];
__device__ float g_gp[BATCH*8*8*2];

// ---------------- helpers ----------------
__device__ __forceinline__ unsigned f2u(float f) {
    unsigned u = __float_as_uint(f);
    return (u & 0x80000000u) ? ~u : (u | 0x80000000u);
}

// ---------------- transpose x [B,3,N] -> xt [B,N,3] ----------------
__global__ void k_transpose(const float* __restrict__ x) {
    int i = blockIdx.x * 256 + threadIdx.x;           // over B*3*N
    if (i < BATCH*3*NPTS) {
        int b = i / (3*NPTS);
        int r = i % (3*NPTS);
        int c = r / NPTS, n = r % NPTS;
        g_xt[(b*NPTS + n)*3 + c] = x[i];
    }
}

// ---------------- squared norms of feature rows ----------------
__global__ void k_sq(int foff) {
    int p = blockIdx.x * 8 + (threadIdx.x >> 5);
    int lane = threadIdx.x & 31;
    if (p < BATCH*NPTS) {
        const float* r = &g_feats[(size_t)p*FEAT + foff];
        float v = r[lane], w = r[lane + 32];
        float s = v*v + w*w;
        #pragma unroll
        for (int o = 16; o; o >>= 1) s += __shfl_xor_sync(~0u, s, o);
        if (lane == 0) g_sq[p] = s;
    }
}

// ---------------- warp-level top-80 radix select over 2048 smem keys ----------------
// No block barriers; one warp owns one point. Histogram in warp-private smem.
// Keep-set matches jax.lax.top_k: all keys > T, plus first (ascending index) of == T.
__device__ __forceinline__ void warp_topk80(const unsigned* __restrict__ sk,
                                            int* __restrict__ hist, int p) {
    const unsigned FULL = 0xFFFFFFFFu;
    int lane = threadIdx.x & 31;
    unsigned prefix = 0, maskacc = 0;
    int kneed = KNN;
    #pragma unroll
    for (int shift = 24; shift >= 0; shift -= 8) {
        #pragma unroll
        for (int i = 0; i < 8; i++) hist[lane*8 + i] = 0;
        __syncwarp();
        #pragma unroll 4
        for (int e = 0; e < 64; e++) {
            unsigned u = sk[(e << 5) + lane];
            if ((u & maskacc) == prefix) atomicAdd(&hist[(u >> shift) & 255], 1);
        }
        __syncwarp();
        // lane owns bins [lane*8, lane*8+8)
        int h[8], lsum = 0;
        #pragma unroll
        for (int i = 0; i < 8; i++) { h[i] = hist[lane*8 + i]; lsum += h[i]; }
        // inclusive suffix scan across lanes (sum over lanes >= lane)
        int v = lsum;
        #pragma unroll
        for (int off = 1; off < 32; off <<= 1) {
            int t = __shfl_down_sync(FULL, v, off);
            if (lane < 32 - off) v += t;
        }
        int run = v - lsum;             // count of bytes in higher lanes (> all my bins)
        int selbyte = -1, selrem = 0;
        #pragma unroll
        for (int i = 7; i >= 0; i--) {  // descending byte value within my chunk
            int incl = run + h[i];
            if (run < kneed && kneed <= incl) { selbyte = lane*8 + i; selrem = kneed - run; }
            run = incl;
        }
        unsigned ball = __ballot_sync(FULL, selbyte >= 0);
        int srcl = __ffs(ball) - 1;
        selbyte = __shfl_sync(FULL, selbyte, srcl);
        selrem  = __shfl_sync(FULL, selrem,  srcl);
        prefix |= ((unsigned)selbyte) << shift;
        maskacc |= (0xFFu << shift);
        kneed = selrem;
        __syncwarp();
    }
    unsigned T = prefix;                // exact 80th-largest key
    int* out = &g_idx[p*KNN];
    int baseG = 0, baseE = 0;
    int totG = KNN - kneed;             // number of keys strictly greater than T
    for (int e = 0; e < 64; e++) {      // ascending (e, lane) == ascending index
        int idx = (e << 5) + lane;
        unsigned u = sk[idx];
        unsigned bg_ = __ballot_sync(FULL, u > T);
        unsigned be_ = __ballot_sync(FULL, u == T);
        unsigned lt = (1u << lane) - 1u;
        if (u > T) {
            out[baseG + __popc(bg_ & lt)] = idx;
        } else if (u == T) {
            int oe = baseE + __popc(be_ & lt);
            if (oe < kneed) out[totG + oe] = idx;
        }
        baseG += __popc(bg_);
        baseE += __popc(be_);
    }
}

// ---------------- kNN layer 1: coordinate keys computed in-warp ----------------
__global__ void __launch_bounds__(32*WPB) k_knn_small() {
    __shared__ unsigned skeys[WPB][NPTS];   // 32 KB
    __shared__ int      shist[WPB][256];    // 4 KB
    int w = threadIdx.x >> 5, lane = threadIdx.x & 31;
    int p = blockIdx.x * WPB + w;           // b*N + n
    int b = p >> 11;
    unsigned* sk = skeys[w];
    const float* base = &g_xt[(b*NPTS)*3];
    float cx = base[(p & 2047)*3 + 0];
    float cy = base[(p & 2047)*3 + 1];
    float cz = base[(p & 2047)*3 + 2];
    for (int i = lane; i < NPTS; i += 32) {
        float X = base[i*3 + 0], Y = base[i*3 + 1], Z = base[i*3 + 2];
        float key = 2.f*(cx*X + cy*Y + cz*Z) - (X*X + Y*Y + Z*Z);
        sk[i] = f2u(key);
    }
    __syncwarp();
    warp_topk80(sk, shist[w], p);
}

// ---------------- kNN layers 2/3: keys from precomputed rows ----------------
__global__ void __launch_bounds__(32*WPB) k_knn_row() {
    __shared__ unsigned skeys[WPB][NPTS];   // 32 KB
    __shared__ int      shist[WPB][256];    // 4 KB
    int w = threadIdx.x >> 5, lane = threadIdx.x & 31;
    int p = blockIdx.x * WPB + w;           // b*N + n
    unsigned* sk = skeys[w];
    const float* row = &g_key[(size_t)p*NPTS];
    for (int i = lane; i < NPTS; i += 32) sk[i] = f2u(row[i]);
    __syncwarp();
    warp_topk80(sk, shist[w], p);
}

// ---------------- key GEMM: key[b,n,m] = 2*<f_n,f_m> - sq[m]  (K=64) ----------------
__global__ void k_key_gemm(int foff) {
    __shared__ float As[8][128], Bs[8][128];
    int b = blockIdx.z;
    int row0 = blockIdx.y * 128, col0 = blockIdx.x * 128;
    int tid = threadIdx.x;
    int tx = tid & 15, ty = tid >> 4;
    const float* Ab = &g_feats[((size_t)(b*NPTS + row0))*FEAT + foff];
    const float* Bb = &g_feats[((size_t)(b*NPTS + col0))*FEAT + foff];
    int lr = tid >> 1, lc = (tid & 1) * 4;
    float acc[8][8] = {};
    for (int k0 = 0; k0 < 64; k0 += 8) {
        float4 av = *(const float4*)(Ab + (size_t)lr*FEAT + k0 + lc);
        float4 bv = *(const float4*)(Bb + (size_t)lr*FEAT + k0 + lc);
        As[lc+0][lr] = av.x; As[lc+1][lr] = av.y; As[lc+2][lr] = av.z; As[lc+3][lr] = av.w;
        Bs[lc+0][lr] = bv.x; Bs[lc+1][lr] = bv.y; Bs[lc+2][lr] = bv.z; Bs[lc+3][lr] = bv.w;
        __syncthreads();
        #pragma unroll
        for (int k = 0; k < 8; k++) {
            float a[8], bb[8];
            #pragma unroll
            for (int i = 0; i < 8; i++) a[i] = As[k][ty*8 + i];
            #pragma unroll
            for (int j = 0; j < 8; j++) bb[j] = Bs[k][tx*8 + j];
            #pragma unroll
            for (int i = 0; i < 8; i++)
                #pragma unroll
                for (int j = 0; j < 8; j++)
                    acc[i][j] += a[i] * bb[j];
        }
        __syncthreads();
    }
    #pragma unroll
    for (int i = 0; i < 8; i++) {
        int r = row0 + ty*8 + i;
        #pragma unroll
        for (int j = 0; j < 8; j++) {
            int c = col0 + tx*8 + j;
            g_key[((size_t)(b*NPTS + r))*NPTS + c] = 2.f*acc[i][j] - g_sq[b*NPTS + c];
        }
    }
}

// ---------------- prep: y = f@Wl^T, c = f@(Wr-Wl)^T  (W is [O,2C]) ----------------
__global__ void k_prep(int use_xt, int foff, int Cin, int O, const float* __restrict__ W) {
    __shared__ float sf[16*64];
    int p0 = blockIdx.x * 16;
    int tid = threadIdx.x;
    for (int i = tid; i < 16*Cin; i += blockDim.x) {
        int rr = i / Cin, cc = i % Cin;
        int p = p0 + rr;
        sf[rr*Cin + cc] = use_xt ? g_xt[p*3 + cc]
                                 : g_feats[(size_t)p*FEAT + foff + cc];
    }
    __syncthreads();
    const float* Wr = &W[tid * 2 * Cin];
    for (int r = 0; r < 16; r++) {
        const float* fr = &sf[r*Cin];
        float y = 0.f, cc2 = 0.f;
        #pragma unroll 4
        for (int c = 0; c < Cin; c++) {
            float fv = fr[c];
            float wl = Wr[c], wrr = Wr[Cin + c];
            y   += fv * wl;
            cc2 += fv * (wrr - wl);
        }
        g_y[(size_t)(p0 + r)*O + tid] = y;
        g_c[(size_t)(p0 + r)*O + tid] = cc2;
    }
}

// ---------------- edge pass: per (b,n,o) max/min over k + per-group partial stats --
__global__ void k_edge(int O) {
    __shared__ int sidx[KNN];
    int p = blockIdx.x;                     // b*N + n
    int tid = threadIdx.x;
    for (int i = tid; i < KNN; i += blockDim.x)
        sidx[i] = g_idx[p*KNN + i];
    __syncthreads();
    int b = p >> 11;
    const float* ybase = &g_y[((size_t)b*NPTS)*O];
    float c = g_c[(size_t)p*O + tid];
    float mx = -FLT_MAX, mn = FLT_MAX, s = 0.f, ss = 0.f;
    #pragma unroll 4
    for (int k = 0; k < KNN; k++) {
        int j = sidx[k];
        float v = ybase[(size_t)j*O + tid] + c;
        mx = fmaxf(mx, v);
        mn = fminf(mn, v);
        s += v;
        ss += v*v;
    }
    #pragma unroll
    for (int o = 16; o; o >>= 1) {
        s  += __shfl_xor_sync(~0u, s,  o);
        ss += __shfl_xor_sync(~0u, ss, o);
    }
    int lane = tid & 31, w = tid >> 5;      // group stats per warp (32 channels)
    int G = O >> 5;
    if (lane == 0) {
        g_pst[((size_t)p*G + w)*2 + 0] = s;
        g_pst[((size_t)p*G + w)*2 + 1] = ss;
    }
    g_hmax[(size_t)p*O + tid] = mx;
    g_hmin[(size_t)p*O + tid] = mn;
}

// ---------------- GN stats reduce (deterministic tree) -> per-channel scale/shift --
__global__ void k_gnstats(int G, int O, const float* __restrict__ gamma,
                          const float* __restrict__ beta) {
    int b = blockIdx.x / G, g = blockIdx.x % G;
    int tid = threadIdx.x;
    float s = 0.f, ss = 0.f;
    for (int n = tid; n < NPTS; n += 256) {
        size_t base = (((size_t)(b*NPTS + n))*G + g)*2;
        s += g_pst[base]; ss += g_pst[base + 1];
    }
    __shared__ float rs[256], rss[256];
    rs[tid] = s; rss[tid] = ss;
    __syncthreads();
    for (int off = 128; off; off >>= 1) {
        if (tid < off) { rs[tid] += rs[tid+off]; rss[tid] += rss[tid+off]; }
        __syncthreads();
    }
    float invc = 1.f / ((float)NPTS * (float)KNN * 32.f);
    float mean = rs[0] * invc;
    float var  = rss[0] * invc - mean*mean;
    float r = rsqrtf(var + EPSV);
    if (tid < 32) {
        int o = g*32 + tid;
        float sg = gamma[o] * r;
        float tt = beta[o] - sg * mean;
        g_ss[(b*O + o)*2 + 0] = sg;
        g_ss[(b*O + o)*2 + 1] = tt;
    }
}

// ---------------- finalize: feats[...,off+o] = lrelu(s*h* + t) ----------------
__global__ void k_edge_final(int O, int off) {
    int i = blockIdx.x*256 + threadIdx.x;   // over B*N*O
    if (i < BATCH*NPTS*O) {
        int p = i / O, o = i % O;
        int b = p >> 11;
        float sg = g_ss[(b*O + o)*2], tt = g_ss[(b*O + o)*2 + 1];
        float h = (sg >= 0.f) ? g_hmax[i] : g_hmin[i];
        float v = sg*h + tt;
        v = (v > 0.f) ? v : 0.2f*v;
        g_feats[(size_t)p*FEAT + off + o] = v;
    }
}

// ---------------- MLP GEMM: h = feats @ Wm^T + bm  (8192x1024x256) ----------------
__global__ void k_mlp_gemm(const float* __restrict__ Wm, const float* __restrict__ bm) {
    __shared__ float As[8][128], Bs[8][128];
    int row0 = blockIdx.y * 128;            // over B*N = 8192
    int col0 = blockIdx.x * 128;            // over 1024
    int tid = threadIdx.x;
    int tx = tid & 15, ty = tid >> 4;
    int lr = tid >> 1, lc = (tid & 1) * 4;
    const float* Ab = &g_feats[(size_t)row0 * FEAT];
    const float* Bb = &Wm[(size_t)col0 * FEAT];
    float acc[8][8] = {};
    for (int k0 = 0; k0 < FEAT; k0 += 8) {
        float4 av = *(const float4*)(Ab + (size_t)lr*FEAT + k0 + lc);
        float4 bv = *(const float4*)(Bb + (size_t)lr*FEAT + k0 + lc);
        As[lc+0][lr] = av.x; As[lc+1][lr] = av.y; As[lc+2][lr] = av.z; As[lc+3][lr] = av.w;
        Bs[lc+0][lr] = bv.x; Bs[lc+1][lr] = bv.y; Bs[lc+2][lr] = bv.z; Bs[lc+3][lr] = bv.w;
        __syncthreads();
        #pragma unroll
        for (int k = 0; k < 8; k++) {
            float a[8], bb[8];
            #pragma unroll
            for (int i = 0; i < 8; i++) a[i] = As[k][ty*8 + i];
            #pragma unroll
            for (int j = 0; j < 8; j++) bb[j] = Bs[k][tx*8 + j];
            #pragma unroll
            for (int i = 0; i < 8; i++)
                #pragma unroll
                for (int j = 0; j < 8; j++)
                    acc[i][j] += a[i] * bb[j];
        }
        __syncthreads();
    }
    #pragma unroll
    for (int i = 0; i < 8; i++) {
        int r = row0 + ty*8 + i;
        #pragma unroll
        for (int j = 0; j < 8; j++) {
            int c = col0 + tx*8 + j;
            g_h[(size_t)r*MLPO + c] = acc[i][j] + bm[c];
        }
    }
}

// ---------------- MLP head partials: per (b,group,seg) stats and per-o max/min ----
__global__ void k_mlp_part() {
    int b = blockIdx.z, g = blockIdx.y, seg = blockIdx.x;
    int t = threadIdx.x;                    // 128 = channels in group
    float mx = -FLT_MAX, mn = FLT_MAX, s = 0.f, ss = 0.f;
    int o = g*128 + t;
    for (int n = seg*256; n < seg*256 + 256; n++) {
        float v = g_h[((size_t)(b*NPTS + n))*MLPO + o];
        mx = fmaxf(mx, v); mn = fminf(mn, v);
        s += v; ss += v*v;
    }
    g_mmax[(b*8 + seg)*MLPO + o] = mx;
    g_mmin[(b*8 + seg)*MLPO + o] = mn;
    __shared__ float rs[128], rss[128];
    rs[t] = s; rss[t] = ss;
    __syncthreads();
    for (int off = 64; off; off >>= 1) {
        if (t < off) { rs[t] += rs[t+off]; rss[t] += rss[t+off]; }
        __syncthreads();
    }
    if (t == 0) {
        g_gp[((b*8 + g)*8 + seg)*2 + 0] = rs[0];
        g_gp[((b*8 + g)*8 + seg)*2 + 1] = rss[0];
    }
}

__global__ void k_mlp_final(const float* __restrict__ gm, const float* __restrict__ bg,
                            float* __restrict__ out4) {
    int b = blockIdx.x >> 3, g = blockIdx.x & 7;
    int t = threadIdx.x;
    int o = g*128 + t;
    float S = 0.f, SS = 0.f;
    #pragma unroll
    for (int seg = 0; seg < 8; seg++) {
        S  += g_gp[((b*8 + g)*8 + seg)*2 + 0];
        SS += g_gp[((b*8 + g)*8 + seg)*2 + 1];
    }
    float mx = -FLT_MAX, mn = FLT_MAX;
    #pragma unroll
    for (int seg = 0; seg < 8; seg++) {
        mx = fmaxf(mx, g_mmax[(b*8 + seg)*MLPO + o]);
        mn = fminf(mn, g_mmin[(b*8 + seg)*MLPO + o]);
    }
    float invc = 1.f / ((float)NPTS * 128.f);
    float mean = S * invc;
    float var  = SS * invc - mean*mean;
    float r = rsqrtf(var + EPSV);
    float sg = gm[o] * r;
    float tt = bg[o] - sg * mean;
    float h = (sg >= 0.f) ? mx : mn;
    float v = sg*h + tt;
    out4[b*MLPO + o] = fmaxf(v, 0.f);
}

// ---------------- feats transpose -> x_features [B,256,N] ----------------
__global__ void k_featsT(float* __restrict__ outf) {
    __shared__ float tile[32][33];
    int c0 = blockIdx.x * 32, n0 = blockIdx.y * 32, b = blockIdx.z;
    for (int i = threadIdx.y; i < 32; i += 8)
        tile[i][threadIdx.x] = g_feats[((size_t)(b*NPTS + n0 + i))*FEAT + c0 + threadIdx.x];
    __syncthreads();
    for (int i = threadIdx.y; i < 32; i += 8)
        outf[((size_t)b*FEAT + c0 + i)*NPTS + n0 + threadIdx.x] = tile[threadIdx.x][i];
}

// ---------------- launch ----------------
extern "C" void kernel_launch(void* const* d_in, const int* in_sizes, int n_in,
                              void* d_out, int out_size) {
    const float* x  = (const float*)d_in[0];
    const float* W1 = (const float*)d_in[1];
    const float* g1 = (const float*)d_in[2];
    const float* b1 = (const float*)d_in[3];
    const float* W2 = (const float*)d_in[4];
    const float* g2 = (const float*)d_in[5];
    const float* b2 = (const float*)d_in[6];
    const float* W3 = (const float*)d_in[7];
    const float* g3 = (const float*)d_in[8];
    const float* b3 = (const float*)d_in[9];
    const float* Wm = (const float*)d_in[10];
    const float* bm = (const float*)d_in[11];
    const float* gm = (const float*)d_in[12];
    const float* bg = (const float*)d_in[13];
    float* out = (float*)d_out;

    k_transpose<<<96, 256>>>(x);

    // Layer 1: C=3 -> O=64, G=2
    k_knn_small<<<BATCH*NPTS/WPB, 32*WPB>>>();
    k_prep<<<BATCH*NPTS/16, 64>>>(1, 0, 3, 64, W1);
    k_edge<<<BATCH*NPTS, 64>>>(64);
    k_gnstats<<<BATCH*2, 256>>>(2, 64, g1, b1);
    k_edge_final<<<BATCH*NPTS*64/256, 256>>>(64, 0);

    // Layer 2: C=64 (x1) -> O=64, G=2
    k_sq<<<BATCH*NPTS/8, 256>>>(0);
    k_key_gemm<<<dim3(16,16,BATCH), 256>>>(0);
    k_knn_row<<<BATCH*NPTS/WPB, 32*WPB>>>();
    k_prep<<<BATCH*NPTS/16, 64>>>(0, 0, 64, 64, W2);
    k_edge<<<BATCH*NPTS, 64>>>(64);
    k_gnstats<<<BATCH*2, 256>>>(2, 64, g2, b2);
    k_edge_final<<<BATCH*NPTS*64/256, 256>>>(64, 64);

    // Layer 3: C=64 (x2) -> O=128, G=4
    k_sq<<<BATCH*NPTS/8, 256>>>(64);
    k_key_gemm<<<dim3(16,16,BATCH), 256>>>(64);
    k_knn_row<<<BATCH*NPTS/WPB, 32*WPB>>>();
    k_prep<<<BATCH*NPTS/16, 128>>>(0, 64, 64, 128, W3);
    k_edge<<<BATCH*NPTS, 128>>>(128);
    k_gnstats<<<BATCH*4, 256>>>(4, 128, g3, b3);
    k_edge_final<<<BATCH*NPTS*128/256, 256>>>(128, 128);

    // MLP head
    k_mlp_gemm<<<dim3(MLPO/128, BATCH*NPTS/128), 256>>>(Wm, bm);
    k_mlp_part<<<dim3(8, 8, BATCH), 128>>>();
    k_mlp_final<<<BATCH*8, 128>>>(gm, bg, out);

    // x_features output
    k_featsT<<<dim3(FEAT/32, NPTS/32, BATCH), dim3(32, 8)>>>(out + BATCH*MLPO);
}